// round 9
// baseline (speedup 1.0000x reference)
#include <cuda_runtime.h>
#include <cuda_fp16.h>

// Problem shape (fixed by the dataset): attn_logprob (B,1,T,L) fp32,
// text_lens (B) int32 in [100,400], mel_lens (B) int32 in [1000,2000].
#define BB 64
#define TT 2000
#define LL 400
#define NTHREADS 256

// Scratch (static device globals; zero-initialized at module load).
__device__ __half d_q[(size_t)BB * TT * LL];   // q_k = exp(x_k - m), only k < tl written
__device__ float2 d_qbl[BB * TT];              // (qblank = exp(-1-m), logpmax = m - lse)
__device__ float  d_loss[BB];

// -------------------------------------------------------------------------
// Kernel 1: per-row max-normalized softmax. One warp per (b,t) row.
//   m  = max(max_k x_k, -1)
//   q_k = exp(x_k - m)  (fp16, k < text_lens[b] only)
//   qblank = exp(-1-m),  logpmax = m - lse = -log(sum_j exp(x_j - m) + exp(-1-m))
// -------------------------------------------------------------------------
__global__ __launch_bounds__(256) void softmax_rows(const float* __restrict__ x,
                                                    const int* __restrict__ text_lens) {
    int warp = blockIdx.x * (blockDim.x >> 5) + (threadIdx.x >> 5);
    int lane = threadIdx.x & 31;
    if (warp >= BB * TT) return;
    int b = warp / TT;
    const float* row = x + (size_t)warp * LL;

    float v[13];
    float m = -1.0f;
#pragma unroll
    for (int i = 0; i < 13; i++) {
        int k = lane + 32 * i;
        v[i] = (k < LL) ? row[k] : -1e30f;
        m = fmaxf(m, v[i]);
    }
#pragma unroll
    for (int o = 16; o; o >>= 1) m = fmaxf(m, __shfl_xor_sync(0xffffffffu, m, o));

    float e[13];
    float s = 0.f;
#pragma unroll
    for (int i = 0; i < 13; i++) {
        e[i] = __expf(v[i] - m);
        int k = lane + 32 * i;
        if (k < LL) s += e[i];
    }
    float qb = __expf(-1.0f - m);
    if (lane == 0) s += qb;
#pragma unroll
    for (int o = 16; o; o >>= 1) s += __shfl_xor_sync(0xffffffffu, s, o);

    int tl = text_lens[b];
#pragma unroll
    for (int i = 0; i < 13; i++) {
        int k = lane + 32 * i;
        if (k < tl) d_q[(size_t)warp * LL + k] = __float2half(e[i]);
    }
    if (lane == 0) d_qbl[warp] = make_float2(qb, -__logf(s));
}

// -------------------------------------------------------------------------
// Kernel 2: CTC forward recurrence, probability domain, one CTA per batch.
// Thread j owns states 4j..4j+3 (stored = true * 2^-E, E per-thread int).
// EVERY step: halo ratio recomputed from the fresh neighbor E, own states
// rescaled toward 2^40. Zero-threads adopt the neighbor's E so first mass
// arrives with d = 0. All scale factors are exact powers of two.
// One barrier per step via double-buffered (n3, E) halo.
// -------------------------------------------------------------------------
__global__ __launch_bounds__(NTHREADS, 1)
void ctc_forward(const int* __restrict__ text_lens, const int* __restrict__ mel_lens) {
    __shared__ float2 qbl_sh[TT];                 // (qblank, logpmax) per t
    __shared__ float2 halo[2][NTHREADS + 1];      // (n3, E-bits), double-buffered
    __shared__ float2 Sfin[804];                  // final (alpha, E-bits) per state

    const int b   = blockIdx.x;
    const int tid = threadIdx.x;
    const int tl  = text_lens[b];
    const int mel = mel_lens[b];
    const int Sb  = 2 * tl + 1;                   // valid states

    const float2* g_qbl = d_qbl + b * TT;
    for (int i = tid; i < mel; i += NTHREADS) qbl_sh[i] = g_qbl[i];
    for (int i = tid; i < NTHREADS + 1; i += NTHREADS) {
        halo[0][i] = make_float2(0.f, __int_as_float(0));
        halo[1][i] = make_float2(0.f, __int_as_float(0));
    }
    __syncthreads();

    const __half* qrow_base = d_q + (size_t)b * TT * LL;
    const int s0 = 4 * tid;
    const bool has_states = (s0 < Sb);
    const bool has_q = (s0 + 1 < Sb);             // 2*tid < tl
    const int kq = 2 * tid;

    // alpha(t=0): a[0]=qblank0, a[1]=q(0,0); all else 0 (tl >= 100 always).
    float a0 = 0.f, a1 = 0.f, a2 = 0.f, a3 = 0.f;
    if (tid == 0) {
        a0 = qbl_sh[0].x;
        a1 = __half2float(qrow_base[0]);
    }
    int   E = 0;
    float sumL = qbl_sh[0].y, comp = 0.f;         // Kahan sum of logpmax

    // Depth-2 prefetch of this thread's q pair.
    __half2 P[2];
    P[0] = __float2half2_rn(0.f);
    P[1] = __float2half2_rn(0.f);
    if (has_q) {
        if (mel > 1) P[0] = *(const __half2*)(qrow_base + (size_t)1 * LL + kq);
        if (mel > 2) P[1] = *(const __half2*)(qrow_base + (size_t)2 * LL + kq);
    }

#pragma unroll 1
    for (int t = 1; t < mel; t++) {
        const int slot = t & 1;
        const float2 ql = qbl_sh[t];
        float2 qv = make_float2(0.f, 0.f);
        if (has_q) {
            qv = __half22float2(P[slot ^ 1]);     // q(t)
            int tn = t + 2;
            if (tn < mel) P[slot ^ 1] = *(const __half2*)(qrow_base + (size_t)tn * LL + kq);
        }

        // Halo conversion: recomputed from scratch EVERY step.
        const float2 h = halo[slot ^ 1][tid];     // neighbor (n3, E) from t-1
        const int E_nb = __float_as_int(h.y);
        int d = E_nb - E;
        d = max(-126, min(126, d));
        const float ratio = __int_as_float((127 + d) << 23);   // exact 2^d
        const float am1 = h.x * ratio;            // alpha_{t-1}[s0-1] in my scale

        const float eb = ql.x, e1 = qv.x, e3 = qv.y;
        float n0 = eb * (a0 + am1);               // even: a[s]+a[s-1]
        float n1 = e1 * (a1 + a0 + am1);          // odd : +a[s-2]
        float n2 = eb * (a2 + a1);
        float n3 = e3 * (a3 + a2 + a1);

        // Per-thread rescale toward 2^40, EVERY step. Zero threads adopt E_nb.
        const float mm = fmaxf(fmaxf(n0, n1), fmaxf(n2, n3));
        if (mm > 0.f) {
            int e4 = ((__float_as_int(mm) >> 23) & 255) - 127;
            int sh = 40 - e4;
            sh = max(-126, min(126, sh));
            const float sc = __int_as_float((127 + sh) << 23);  // exact 2^sh
            n0 *= sc; n1 *= sc; n2 *= sc; n3 *= sc;
            E -= sh;
        } else {
            E = E_nb;                              // stay in neighbor's scale
        }
        a0 = n0; a1 = n1; a2 = n2; a3 = n3;

        halo[slot][1 + tid] = make_float2(n3, __int_as_float(E));
        __syncthreads();

        // Kahan accumulate logpmax(t)
        float y = ql.y - comp;
        float tsum = sumL + y;
        comp = (tsum - sumL) - y;
        sumL = tsum;
    }

    // Dump valid final states (value, per-thread E) and finish in double.
    if (has_states) {
        float2 ev = make_float2(0.f, __int_as_float(E));
        ev.x = a0;                 Sfin[s0]     = ev;
        if (s0 + 1 < Sb) { ev.x = a1; Sfin[s0 + 1] = ev; }
        if (s0 + 2 < Sb) { ev.x = a2; Sfin[s0 + 2] = ev; }
        if (s0 + 3 < Sb) { ev.x = a3; Sfin[s0 + 3] = ev; }
    }
    __syncthreads();
    if (tid == 0) {
        const double LN2 = 0.6931471805599453;
        float2 vh = Sfin[2 * tl];
        float2 vl = Sfin[2 * tl - 1];
        double lh = (vh.x > 0.f) ? log((double)vh.x) + (double)__float_as_int(vh.y) * LN2 : -1e300;
        double ll = (vl.x > 0.f) ? log((double)vl.x) + (double)__float_as_int(vl.y) * LN2 : -1e300;
        double mx = fmax(lh, ll), mn = fmin(lh, ll);
        double la = mx + log1p(exp(mn - mx)) + (double)sumL;
        float loss = (la > -5e29) ? (float)(-la / (double)tl) : 0.f;
        d_loss[b] = loss;
    }
}

// -------------------------------------------------------------------------
// Kernel 3: mean over B losses (deterministic warp reduction).
// -------------------------------------------------------------------------
__global__ void reduce_loss(float* __restrict__ out) {
    int lane = threadIdx.x;
    float s = d_loss[lane] + d_loss[lane + 32];
#pragma unroll
    for (int o = 16; o; o >>= 1) s += __shfl_xor_sync(0xffffffffu, s, o);
    if (lane == 0) out[0] = s * (1.0f / (float)BB);
}

extern "C" void kernel_launch(void* const* d_in, const int* in_sizes, int n_in,
                              void* d_out, int out_size) {
    const float* x    = (const float*)d_in[0];
    const int*   tlen = (const int*)d_in[1];
    const int*   mlen = (const int*)d_in[2];
    (void)in_sizes; (void)n_in; (void)out_size;

    const int rows = BB * TT;              // 128000
    const int wpb  = 8;                    // 8 warps (rows) per block
    softmax_rows<<<rows / wpb, wpb * 32>>>(x, tlen);
    ctc_forward<<<BB, NTHREADS>>>(tlen, mlen);
    reduce_loss<<<1, 32>>>((float*)d_out);
}

// round 10
// speedup vs baseline: 1.3255x; 1.3255x over previous
#include <cuda_runtime.h>
#include <cuda_fp16.h>

// Problem shape (fixed by the dataset): attn_logprob (B,1,T,L) fp32,
// text_lens (B) int32 in [100,400], mel_lens (B) int32 in [1000,2000].
#define BB 64
#define TT 2000
#define LL 400
#define NTHREADS 256

// Scratch (static device globals; zero-initialized at module load).
__device__ __half d_q[(size_t)BB * TT * LL];   // q_k = exp(x_k - m), only k < tl written
__device__ float2 d_qbl[BB * TT];              // (qblank = exp(-1-m), logpmax = m - lse)
__device__ float  d_loss[BB];

// -------------------------------------------------------------------------
// Kernel 1: per-row max-normalized softmax. One warp per (b,t) row.
//   m  = max(max_k x_k, -1)
//   q_k = exp(x_k - m)  (fp16, k < text_lens[b] only)
//   qblank = exp(-1-m),  logpmax = m - lse
// HBM-bound at ~71% DRAM already (45.6 us) — unchanged.
// -------------------------------------------------------------------------
__global__ __launch_bounds__(256) void softmax_rows(const float* __restrict__ x,
                                                    const int* __restrict__ text_lens) {
    int warp = blockIdx.x * (blockDim.x >> 5) + (threadIdx.x >> 5);
    int lane = threadIdx.x & 31;
    if (warp >= BB * TT) return;
    int b = warp / TT;
    const float* row = x + (size_t)warp * LL;

    float v[13];
    float m = -1.0f;
#pragma unroll
    for (int i = 0; i < 13; i++) {
        int k = lane + 32 * i;
        v[i] = (k < LL) ? row[k] : -1e30f;
        m = fmaxf(m, v[i]);
    }
#pragma unroll
    for (int o = 16; o; o >>= 1) m = fmaxf(m, __shfl_xor_sync(0xffffffffu, m, o));

    float e[13];
    float s = 0.f;
#pragma unroll
    for (int i = 0; i < 13; i++) {
        e[i] = __expf(v[i] - m);
        int k = lane + 32 * i;
        if (k < LL) s += e[i];
    }
    float qb = __expf(-1.0f - m);
    if (lane == 0) s += qb;
#pragma unroll
    for (int o = 16; o; o >>= 1) s += __shfl_xor_sync(0xffffffffu, s, o);

    int tl = text_lens[b];
#pragma unroll
    for (int i = 0; i < 13; i++) {
        int k = lane + 32 * i;
        if (k < tl) d_q[(size_t)warp * LL + k] = __float2half(e[i]);
    }
    if (lane == 0) d_qbl[warp] = make_float2(qb, -__logf(s));
}

// -------------------------------------------------------------------------
// Kernel 2: CTC forward recurrence, probability domain, one CTA per batch.
// Thread j owns states 4j..4j+3 (stored = true * 2^-E, E per-thread int).
// EVERY step: halo ratio recomputed from fresh neighbor E; own states
// rescaled toward 2^40. All scale factors exact powers of two.
// One barrier per step via double-buffered (n3, E) halo.
// NEW vs R9: depth-8 register prefetch of q (unroll x8, constant indices)
// to fully hide DRAM latency behind ~8 step-times; logpmax summation moved
// out of the loop into a post-loop parallel reduction.
// -------------------------------------------------------------------------
__global__ __launch_bounds__(NTHREADS, 1)
void ctc_forward(const int* __restrict__ text_lens, const int* __restrict__ mel_lens) {
    __shared__ float  qb_sh[TT];                  // qblank per t
    __shared__ float  lpm_sh[TT];                 // logpmax per t (summed post-loop)
    __shared__ float2 halo[2][NTHREADS + 1];      // (n3, E-bits), double-buffered
    __shared__ float2 Sfin[804];                  // final (alpha, E-bits) per state
    __shared__ double red_sh[8];

    const int b   = blockIdx.x;
    const int tid = threadIdx.x;
    const int tl  = text_lens[b];
    const int mel = mel_lens[b];
    const int Sb  = 2 * tl + 1;                   // valid states

    const float2* g_qbl = d_qbl + b * TT;
    for (int i = tid; i < mel; i += NTHREADS) {
        float2 v = g_qbl[i];
        qb_sh[i]  = v.x;
        lpm_sh[i] = v.y;
    }
    for (int i = tid; i < NTHREADS + 1; i += NTHREADS) {
        halo[0][i] = make_float2(0.f, __int_as_float(0));
        halo[1][i] = make_float2(0.f, __int_as_float(0));
    }
    __syncthreads();

    const __half* qrow_base = d_q + (size_t)b * TT * LL;
    const int s0 = 4 * tid;
    const bool has_states = (s0 < Sb);
    const bool has_q = (s0 + 1 < Sb);             // 2*tid < tl
    const int kq = 2 * tid;

    // alpha(t=0): a[0]=qblank0, a[1]=q(0,0); all else 0 (tl >= 100 always).
    float a0 = 0.f, a1 = 0.f, a2 = 0.f, a3 = 0.f;
    if (tid == 0) {
        a0 = qb_sh[0];
        a1 = __half2float(qrow_base[0]);
    }
    int E = 0;

    // Depth-8 register prefetch: P[i] holds q(t = base + i), refilled at +8.
    __half2 P[8];
#pragma unroll
    for (int i = 0; i < 8; i++) {
        P[i] = __float2half2_rn(0.f);
        int ti = 1 + i;
        if (has_q && ti < mel) P[i] = *(const __half2*)(qrow_base + (size_t)ti * LL + kq);
    }

#define STEP(t_, pi_) do {                                                      \
    const int slot_ = (t_) & 1;                                                 \
    const float eb_ = qb_sh[t_];                                                \
    float2 qv_ = make_float2(0.f, 0.f);                                         \
    if (has_q) {                                                                \
        qv_ = __half22float2(P[pi_]);                                           \
        int tn_ = (t_) + 8;                                                     \
        if (tn_ < mel) P[pi_] = *(const __half2*)(qrow_base + (size_t)tn_ * LL + kq); \
    }                                                                           \
    const float2 h_ = halo[slot_ ^ 1][tid];                                     \
    const int Enb_ = __float_as_int(h_.y);                                      \
    int dd_ = Enb_ - E; dd_ = max(-126, min(126, dd_));                         \
    const float ratio_ = __int_as_float((127 + dd_) << 23);                     \
    const float am1_ = h_.x * ratio_;                                           \
    float n0_ = eb_ * (a0 + am1_);                                              \
    float n1_ = qv_.x * (a1 + a0 + am1_);                                       \
    float n2_ = eb_ * (a2 + a1);                                                \
    float n3_ = qv_.y * (a3 + a2 + a1);                                         \
    const float mm_ = fmaxf(fmaxf(n0_, n1_), fmaxf(n2_, n3_));                  \
    if (mm_ > 0.f) {                                                            \
        int e4_ = ((__float_as_int(mm_) >> 23) & 255) - 127;                    \
        int sh_ = 40 - e4_; sh_ = max(-126, min(126, sh_));                     \
        const float sc_ = __int_as_float((127 + sh_) << 23);                    \
        n0_ *= sc_; n1_ *= sc_; n2_ *= sc_; n3_ *= sc_;                         \
        E -= sh_;                                                               \
    } else { E = Enb_; }                                                        \
    a0 = n0_; a1 = n1_; a2 = n2_; a3 = n3_;                                     \
    halo[slot_][1 + tid] = make_float2(n3_, __int_as_float(E));                 \
    __syncthreads();                                                            \
} while (0)

    int t = 1;
#pragma unroll 1
    for (; t + 7 < mel; t += 8) {
        STEP(t, 0); STEP(t + 1, 1); STEP(t + 2, 2); STEP(t + 3, 3);
        STEP(t + 4, 4); STEP(t + 5, 5); STEP(t + 6, 6); STEP(t + 7, 7);
    }
    if (t < mel) { STEP(t, 0); t++; }
    if (t < mel) { STEP(t, 1); t++; }
    if (t < mel) { STEP(t, 2); t++; }
    if (t < mel) { STEP(t, 3); t++; }
    if (t < mel) { STEP(t, 4); t++; }
    if (t < mel) { STEP(t, 5); t++; }
    if (t < mel) { STEP(t, 6); t++; }
#undef STEP

    // Dump valid final states (value, per-thread E).
    if (has_states) {
        float2 ev = make_float2(0.f, __int_as_float(E));
        ev.x = a0;                 Sfin[s0]     = ev;
        if (s0 + 1 < Sb) { ev.x = a1; Sfin[s0 + 1] = ev; }
        if (s0 + 2 < Sb) { ev.x = a2; Sfin[s0 + 2] = ev; }
        if (s0 + 3 < Sb) { ev.x = a3; Sfin[s0 + 3] = ev; }
    }

    // Parallel sum of logpmax over t = 0..mel-1 (double partials).
    double acc = 0.0;
    for (int i = tid; i < mel; i += NTHREADS) acc += (double)lpm_sh[i];
#pragma unroll
    for (int o = 16; o; o >>= 1) acc += __shfl_xor_sync(0xffffffffu, acc, o);
    if ((tid & 31) == 0) red_sh[tid >> 5] = acc;
    __syncthreads();

    if (tid == 0) {
        double sumL = 0.0;
#pragma unroll
        for (int w = 0; w < 8; w++) sumL += red_sh[w];
        const double LN2 = 0.6931471805599453;
        float2 vh = Sfin[2 * tl];
        float2 vl = Sfin[2 * tl - 1];
        double lh = (vh.x > 0.f) ? log((double)vh.x) + (double)__float_as_int(vh.y) * LN2 : -1e300;
        double ll = (vl.x > 0.f) ? log((double)vl.x) + (double)__float_as_int(vl.y) * LN2 : -1e300;
        double mx = fmax(lh, ll), mn = fmin(lh, ll);
        double la = mx + log1p(exp(mn - mx)) + sumL;
        float loss = (la > -5e29) ? (float)(-la / (double)tl) : 0.f;
        d_loss[b] = loss;
    }
}

// -------------------------------------------------------------------------
// Kernel 3: mean over B losses (deterministic warp reduction).
// -------------------------------------------------------------------------
__global__ void reduce_loss(float* __restrict__ out) {
    int lane = threadIdx.x;
    float s = d_loss[lane] + d_loss[lane + 32];
#pragma unroll
    for (int o = 16; o; o >>= 1) s += __shfl_xor_sync(0xffffffffu, s, o);
    if (lane == 0) out[0] = s * (1.0f / (float)BB);
}

extern "C" void kernel_launch(void* const* d_in, const int* in_sizes, int n_in,
                              void* d_out, int out_size) {
    const float* x    = (const float*)d_in[0];
    const int*   tlen = (const int*)d_in[1];
    const int*   mlen = (const int*)d_in[2];
    (void)in_sizes; (void)n_in; (void)out_size;

    const int rows = BB * TT;              // 128000
    const int wpb  = 8;                    // 8 warps (rows) per block
    softmax_rows<<<rows / wpb, wpb * 32>>>(x, tlen);
    ctc_forward<<<BB, NTHREADS>>>(tlen, mlen);
    reduce_loss<<<1, 32>>>((float*)d_out);
}

// round 15
// speedup vs baseline: 3.6521x; 2.7553x over previous
#include <cuda_runtime.h>
#include <cuda_fp16.h>

// Problem shape (fixed by the dataset): attn_logprob (B,1,T,L) fp32,
// text_lens (B) int32 in [100,400], mel_lens (B) int32 in [1000,2000].
#define BB 64
#define TT 2000
#define LL 400
#define NWARP 8
#define KC 16   // time-steps per chunk (per barrier)

// Scratch (static device globals; zero-initialized at module load).
// d_qf[b][t][k] = exp(x[b,t,k] - m) for k < text_lens[b]; 0 elsewhere (zero-init).
__device__ float  d_qf[(size_t)BB * TT * LL];   // 204.8 MB
__device__ float2 d_qbl[BB * TT];               // (qblank = exp(-1-m), logpmax = m - lse)
__device__ float  d_loss[BB];

// -------------------------------------------------------------------------
// Kernel 1: per-row max-normalized softmax. One warp per (b,t) row.
// Proven HBM-bound at ~70% DRAM (46 us) — unchanged.
// -------------------------------------------------------------------------
__global__ __launch_bounds__(256) void softmax_rows(const float* __restrict__ x,
                                                    const int* __restrict__ text_lens) {
    int warp = blockIdx.x * (blockDim.x >> 5) + (threadIdx.x >> 5);
    int lane = threadIdx.x & 31;
    if (warp >= BB * TT) return;
    int b = warp / TT;
    const float* row = x + (size_t)warp * LL;

    float v[13];
    float m = -1.0f;
#pragma unroll
    for (int i = 0; i < 13; i++) {
        int k = lane + 32 * i;
        v[i] = (k < LL) ? row[k] : -1e30f;
        m = fmaxf(m, v[i]);
    }
#pragma unroll
    for (int o = 16; o; o >>= 1) m = fmaxf(m, __shfl_xor_sync(0xffffffffu, m, o));

    float e[13];
    float s = 0.f;
#pragma unroll
    for (int i = 0; i < 13; i++) {
        e[i] = __expf(v[i] - m);
        int k = lane + 32 * i;
        if (k < LL) s += e[i];
    }
    float qb = __expf(-1.0f - m);
    if (lane == 0) s += qb;
#pragma unroll
    for (int o = 16; o; o >>= 1) s += __shfl_xor_sync(0xffffffffu, s, o);

    int tl = text_lens[b];
#pragma unroll
    for (int i = 0; i < 13; i++) {
        int k = lane + 32 * i;
        if (k < tl) d_qf[(size_t)warp * LL + k] = e[i];
    }
    if (lane == 0) d_qbl[warp] = make_float2(qb, -__logf(s));
}

// -------------------------------------------------------------------------
// Kernel 2: CTC forward, probability domain, time-skewed wavefront.
// One CTA per batch, 8 warps. Warp w owns states [128w, 128w+128);
// lane owns 4 states a0..a3 stored as true * 2^-E (per-lane int E) —
// EXACTLY the R10-proven G=4 numerics (fp32-safe spread, bounded dd).
// Intra-warp halo: 2 shuffles/step. Inter-warp halo: warp w runs K=16
// steps behind warp w-1; producer lane31 deposits (a3,E) per step into a
// depth-3 smem ring; consumer preloads a chunk after each barrier.
// __syncthreads() only once per 16 steps.
// -------------------------------------------------------------------------
__global__ __launch_bounds__(256, 1)
void ctc_forward(const int* __restrict__ text_lens, const int* __restrict__ mel_lens) {
    __shared__ float  qb_sh[TT];                 // qblank per t
    __shared__ float2 ring[3][NWARP][KC];        // (a3, E-bits) per producer step
    __shared__ float2 Sfin[1024];                // final (alpha, E-bits) per state
    __shared__ double red_sh[NWARP];

    const int b    = blockIdx.x;
    const int tid  = threadIdx.x;
    const int w    = tid >> 5;
    const int lane = tid & 31;
    const int tl   = text_lens[b];
    const int mel  = mel_lens[b];

    const float2* g_qbl = d_qbl + b * TT;
    for (int i = tid; i < mel; i += 256) qb_sh[i] = g_qbl[i].x;
    __syncthreads();

    const float* qpb = d_qf + (size_t)b * TT * LL;
    // Lane's odd states s0+1, s0+3 -> labels 64w+2lane+1, +2 -> q cols kq, kq+1.
    const int kq = 64 * w + 2 * lane;
    const bool hq = (kq < LL);                   // kq even, so kq+1 <= 399

    float a0 = 0.f, a1 = 0.f, a2 = 0.f, a3 = 0.f;
    int E = 0;
    if (w == 0 && lane == 0) {
        a0 = qb_sh[0];                           // alpha0[0] = qblank(0)
        a1 = qpb[0];                             // alpha0[1] = q(0, label 1)
    }

    const int steps = mel - 1;                   // t = 1 .. mel-1
    const int nch = (steps + KC - 1) / KC;
    const int R = nch + NWARP - 1;

#pragma unroll 1
    for (int r = 0; r < R; r++) {
        const int c = r - w;                     // this warp's chunk index
        const bool go = (c >= 0) && (c < nch);
        if (go) {
            const int t0  = 1 + c * KC;
            const int par = c % 3;               // ring slot of chunk c
            const int pam = (c + 2) % 3;         // ring slot of chunk c-1

            // Preload producer halo entries for this chunk (broadcast LDS).
            // rv[j] = producer state AFTER its step t0+j-1.
            float2 rv[KC];
            const int wp = (w > 0) ? (w - 1) : 0;
            rv[0] = (c == 0) ? make_float2(0.f, __int_as_float(0))
                             : ring[pam][wp][KC - 1];
#pragma unroll
            for (int j = 1; j < KC; j++) rv[j] = ring[par][wp][j - 1];

            // Preload this chunk's emissions (MLP=16).
            float2 ev[KC];
#pragma unroll
            for (int j = 0; j < KC; j++) {
                int t = t0 + j;
                ev[j] = (hq && t < mel) ? *(const float2*)(qpb + (size_t)t * LL + kq)
                                        : make_float2(0.f, 0.f);
            }

#pragma unroll
            for (int j = 0; j < KC; j++) {
                const int t = t0 + j;
                if (t < mel) {
                    const float eb = qb_sh[t];
                    const float e1 = ev[j].x, e3 = ev[j].y;
                    // Halo: shuffles for lanes 1..31; ring regs for lane 0.
                    const float sv = __shfl_up_sync(0xffffffffu, a3, 1);
                    const int   sE = __shfl_up_sync(0xffffffffu, E, 1);
                    float hv; int hE;
                    if (lane == 0) {
                        if (w == 0) { hv = 0.f; hE = E; }
                        else        { hv = rv[j].x; hE = __float_as_int(rv[j].y); }
                    } else { hv = sv; hE = sE; }
                    int dd = hE - E;
                    dd = max(-126, min(126, dd));
                    const float ratio = __int_as_float((127 + dd) << 23);   // exact 2^dd
                    const float am1 = hv * ratio;

                    const float p0 = a0 + am1;
                    const float p1 = a1 + p0;     // a1 + a0 + am1
                    const float p2 = a2 + a1;
                    const float p3 = a3 + p2;     // a3 + a2 + a1
                    const float n0 = eb * p0;
                    const float n1 = e1 * p1;
                    const float n2 = eb * p2;
                    const float n3 = e3 * p3;

                    // Per-lane rescale toward 2^40, every step (branch-free).
                    int mb = max(max(__float_as_int(n0), __float_as_int(n1)),
                                 max(__float_as_int(n2), __float_as_int(n3)));
                    const bool act = (mb > 0);
                    int e4 = (mb >> 23) - 127;
                    int shv = act ? max(-126, min(126, 40 - e4)) : 0;
                    const float sc = __int_as_float((127 + shv) << 23);     // exact 2^shv
                    a0 = n0 * sc; a1 = n1 * sc; a2 = n2 * sc; a3 = n3 * sc;
                    E = act ? (E - shv) : hE;

                    if (lane == 31) ring[par][w][j] = make_float2(a3, __int_as_float(E));
                }
            }
        }
        __syncthreads();
    }

    // Dump final states (value, per-lane E).
    {
        const int s0 = 128 * w + 4 * lane;
        const float Eb = __int_as_float(E);
        Sfin[s0 + 0] = make_float2(a0, Eb);
        Sfin[s0 + 1] = make_float2(a1, Eb);
        Sfin[s0 + 2] = make_float2(a2, Eb);
        Sfin[s0 + 3] = make_float2(a3, Eb);
    }

    // Parallel sum of logpmax over t = 0..mel-1 (double partials).
    double acc = 0.0;
    for (int i = tid; i < mel; i += 256) acc += (double)g_qbl[i].y;
#pragma unroll
    for (int o = 16; o; o >>= 1) acc += __shfl_xor_sync(0xffffffffu, acc, o);
    if (lane == 0) red_sh[w] = acc;
    __syncthreads();

    if (tid == 0) {
        double sumL = 0.0;
#pragma unroll
        for (int i = 0; i < NWARP; i++) sumL += red_sh[i];
        const double LN2 = 0.6931471805599453;
        float2 vh = Sfin[2 * tl];
        float2 vl = Sfin[2 * tl - 1];
        double lh = (vh.x > 0.f) ? log((double)vh.x) + (double)__float_as_int(vh.y) * LN2 : -1e300;
        double ll = (vl.x > 0.f) ? log((double)vl.x) + (double)__float_as_int(vl.y) * LN2 : -1e300;
        double mx = fmax(lh, ll), mn = fmin(lh, ll);
        double la = mx + log1p(exp(mn - mx)) + sumL;
        float loss = (la > -5e29) ? (float)(-la / (double)tl) : 0.f;
        d_loss[b] = loss;
    }
}

// -------------------------------------------------------------------------
// Kernel 3: mean over B losses (deterministic warp reduction).
// -------------------------------------------------------------------------
__global__ void reduce_loss(float* __restrict__ out) {
    int lane = threadIdx.x;
    float s = d_loss[lane] + d_loss[lane + 32];
#pragma unroll
    for (int o = 16; o; o >>= 1) s += __shfl_xor_sync(0xffffffffu, s, o);
    if (lane == 0) out[0] = s * (1.0f / (float)BB);
}

extern "C" void kernel_launch(void* const* d_in, const int* in_sizes, int n_in,
                              void* d_out, int out_size) {
    const float* x    = (const float*)d_in[0];
    const int*   tlen = (const int*)d_in[1];
    const int*   mlen = (const int*)d_in[2];
    (void)in_sizes; (void)n_in; (void)out_size;

    const int rows = BB * TT;              // 128000
    const int wpb  = 8;                    // 8 warps (rows) per block
    softmax_rows<<<rows / wpb, wpb * 32>>>(x, tlen);
    ctc_forward<<<BB, 256>>>(tlen, mlen);
    reduce_loss<<<1, 32>>>((float*)d_out);
}

// round 17
// speedup vs baseline: 3.7004x; 1.0132x over previous
#include <cuda_runtime.h>
#include <cuda_fp16.h>

// Problem shape (fixed by the dataset): attn_logprob (B,1,T,L) fp32,
// text_lens (B) int32 in [100,400], mel_lens (B) int32 in [1000,2000].
#define BB 64
#define TT 2000
#define LL 400
#define NWARP 8
#define KC 16   // time-steps per chunk (per barrier)

// Scratch (static device globals; zero-initialized at module load).
// d_q[b][t][k] = exp(x[b,t,k] - m) fp16 for k < text_lens[b]; 0 elsewhere.
__device__ __half d_q[(size_t)BB * TT * LL];    // 102.4 MB
__device__ float2 d_qbl[BB * TT];               // (qblank = exp(-1-m), logpmax = m - lse)
__device__ float  d_loss[BB];

// -------------------------------------------------------------------------
// Kernel 1: per-row max-normalized softmax. One warp per (b,t) row.
//   m = max(max_k x_k, -1); q_k = exp(x_k - m) (fp16, k < tl only)
//   qblank = exp(-1-m); logpmax = -log(sum_j exp(x_j - m) + exp(-1-m))
// HBM-bound; fp16 q writes cut traffic to ~330 MB -> ~42 us.
// -------------------------------------------------------------------------
__global__ __launch_bounds__(256) void softmax_rows(const float* __restrict__ x,
                                                    const int* __restrict__ text_lens) {
    int warp = blockIdx.x * (blockDim.x >> 5) + (threadIdx.x >> 5);
    int lane = threadIdx.x & 31;
    if (warp >= BB * TT) return;
    int b = warp / TT;
    const float* row = x + (size_t)warp * LL;

    float v[13];
    float m = -1.0f;
#pragma unroll
    for (int i = 0; i < 13; i++) {
        int k = lane + 32 * i;
        v[i] = (k < LL) ? row[k] : -1e30f;
        m = fmaxf(m, v[i]);
    }
#pragma unroll
    for (int o = 16; o; o >>= 1) m = fmaxf(m, __shfl_xor_sync(0xffffffffu, m, o));

    float e[13];
    float s = 0.f;
#pragma unroll
    for (int i = 0; i < 13; i++) {
        e[i] = __expf(v[i] - m);
        int k = lane + 32 * i;
        if (k < LL) s += e[i];
    }
    float qb = __expf(-1.0f - m);
    if (lane == 0) s += qb;
#pragma unroll
    for (int o = 16; o; o >>= 1) s += __shfl_xor_sync(0xffffffffu, s, o);

    int tl = text_lens[b];
#pragma unroll
    for (int i = 0; i < 13; i++) {
        int k = lane + 32 * i;
        if (k < tl) d_q[(size_t)warp * LL + k] = __float2half(e[i]);
    }
    if (lane == 0) d_qbl[warp] = make_float2(qb, -__logf(s));
}

// -------------------------------------------------------------------------
// Kernel 2: CTC forward, probability domain, time-skewed wavefront.
// One CTA per batch, 8 warps; warp w owns states [128w, 128w+128); lane
// owns 4 states (a0..a3) stored as true * 2^-E, per-lane int E (proven
// G=4 numerics). Intra-warp halo: 2 shuffles/step. Inter-warp halo: warp
// w runs 16 steps behind warp w-1 via a depth-3 smem ring; one
// __syncthreads per 16 steps.
// NEW vs R15: (1) emissions double-buffered one chunk ahead (no DRAM
// stall at chunk start); (2) rescale only every 4th step (off the
// cross-lane chain 3/4 of the time); (3) fp16 emissions.
// -------------------------------------------------------------------------
__global__ __launch_bounds__(256, 1)
void ctc_forward(const int* __restrict__ text_lens, const int* __restrict__ mel_lens) {
    __shared__ float  qb_sh[TT];                 // qblank per t
    __shared__ float2 ring[3][NWARP][KC];        // (a3, E-bits) per producer step
    __shared__ float2 Sfin[1024];                // final (alpha, E-bits) per state
    __shared__ double red_sh[NWARP];

    const int b    = blockIdx.x;
    const int tid  = threadIdx.x;
    const int w    = tid >> 5;
    const int lane = tid & 31;
    const int tl   = text_lens[b];
    const int mel  = mel_lens[b];

    const float2* g_qbl = d_qbl + b * TT;
    for (int i = tid; i < mel; i += 256) qb_sh[i] = g_qbl[i].x;
    __syncthreads();

    const __half* qpb = d_q + (size_t)b * TT * LL;
    // Lane's odd states -> labels 64w+2lane+1, +2 -> q cols kq, kq+1.
    const int kq = 64 * w + 2 * lane;
    const bool hq = (kq < LL);

    float a0 = 0.f, a1 = 0.f, a2 = 0.f, a3 = 0.f;
    int E = 0;
    if (w == 0 && lane == 0) {
        a0 = qb_sh[0];                           // alpha0[0] = qblank(0)
        a1 = __half2float(qpb[0]);               // alpha0[1] = q(0, label 1)
    }

    const int steps = mel - 1;                   // t = 1 .. mel-1
    const int nch = (steps + KC - 1) / KC;
    const int R = nch + NWARP - 1;

    __half2 QA[KC], QB[KC];

#define LOADQ(BUF, c_) do {                                                     \
    const int tq0_ = 1 + (c_) * KC;                                             \
    _Pragma("unroll")                                                           \
    for (int j_ = 0; j_ < KC; j_++) {                                           \
        int tq_ = tq0_ + j_;                                                    \
        BUF[j_] = (hq && tq_ < mel)                                             \
            ? *(const __half2*)(qpb + (size_t)tq_ * LL + kq)                    \
            : __float2half2_rn(0.f);                                            \
    }                                                                           \
} while (0)

#define STEP(BUF, j_, RESC_) do {                                               \
    const int t_ = t0 + (j_);                                                   \
    if (t_ < mel) {                                                             \
        const float eb_ = qb_sh[t_];                                            \
        const float2 e13_ = __half22float2(BUF[j_]);                            \
        const float sv_ = __shfl_up_sync(0xffffffffu, a3, 1);                   \
        const int   sE_ = __shfl_up_sync(0xffffffffu, E, 1);                    \
        float hv_; int hE_;                                                     \
        if (lane == 0) {                                                        \
            if (w == 0) { hv_ = 0.f; hE_ = E; }                                 \
            else        { hv_ = rv[j_].x; hE_ = __float_as_int(rv[j_].y); }     \
        } else { hv_ = sv_; hE_ = sE_; }                                        \
        int dd_ = hE_ - E;                                                      \
        dd_ = max(-126, min(126, dd_));                                         \
        const float ratio_ = __int_as_float((127 + dd_) << 23);                 \
        const float am1_ = hv_ * ratio_;                                        \
        const float p0_ = a0 + am1_;                                            \
        const float p1_ = a1 + p0_;                                             \
        const float p2_ = a2 + a1;                                              \
        const float p3_ = a3 + p2_;                                             \
        const float n0_ = eb_ * p0_;                                            \
        const float n1_ = e13_.x * p1_;                                         \
        const float n2_ = eb_ * p2_;                                            \
        const float n3_ = e13_.y * p3_;                                         \
        if (RESC_) {                                                            \
            int mb_ = max(max(__float_as_int(n0_), __float_as_int(n1_)),        \
                          max(__float_as_int(n2_), __float_as_int(n3_)));       \
            const bool act_ = (mb_ > 0);                                        \
            int e4_ = (mb_ >> 23) - 127;                                        \
            int shv_ = act_ ? max(-126, min(126, 40 - e4_)) : 0;                \
            const float sc_ = __int_as_float((127 + shv_) << 23);               \
            a0 = n0_ * sc_; a1 = n1_ * sc_; a2 = n2_ * sc_; a3 = n3_ * sc_;     \
            E = act_ ? (E - shv_) : hE_;                                        \
        } else {                                                                \
            a0 = n0_; a1 = n1_; a2 = n2_; a3 = n3_;                             \
        }                                                                       \
        if (lane == 31) ring[par][w][j_] = make_float2(a3, __int_as_float(E));  \
    }                                                                           \
} while (0)

#define RUN16(BUF) do {                                                         \
    STEP(BUF, 0, 0);  STEP(BUF, 1, 0);  STEP(BUF, 2, 0);  STEP(BUF, 3, 1);      \
    STEP(BUF, 4, 0);  STEP(BUF, 5, 0);  STEP(BUF, 6, 0);  STEP(BUF, 7, 1);      \
    STEP(BUF, 8, 0);  STEP(BUF, 9, 0);  STEP(BUF, 10, 0); STEP(BUF, 11, 1);     \
    STEP(BUF, 12, 0); STEP(BUF, 13, 0); STEP(BUF, 14, 0); STEP(BUF, 15, 1);     \
} while (0)

#pragma unroll 1
    for (int r = 0; r < R; r++) {
        const int c = r - w;                     // this warp's chunk index
        if (c >= 0 && c < nch) {
            const int t0  = 1 + c * KC;
            const int par = c % 3;               // ring slot of chunk c
            const int pam = (c + 2) % 3;         // ring slot of chunk c-1

            // Producer halo entries (broadcast LDS); rv[j] = producer state
            // AFTER its step t0+j-1.
            float2 rv[KC];
            const int wp = (w > 0) ? (w - 1) : 0;
            rv[0] = (c == 0) ? make_float2(0.f, __int_as_float(0))
                             : ring[pam][wp][KC - 1];
#pragma unroll
            for (int j = 1; j < KC; j++) rv[j] = ring[par][wp][j - 1];

            if (c == 0) LOADQ(QA, 0);            // one-time stall on first chunk
            const bool even = ((c & 1) == 0);
            if (c + 1 < nch) {                   // prefetch next chunk's emissions
                if (even) LOADQ(QB, c + 1); else LOADQ(QA, c + 1);
            }
            if (even) { RUN16(QA); } else { RUN16(QB); }
        }
        __syncthreads();
    }
#undef RUN16
#undef STEP
#undef LOADQ

    // Dump final states (value, per-lane E).
    {
        const int s0 = 128 * w + 4 * lane;
        const float Eb = __int_as_float(E);
        Sfin[s0 + 0] = make_float2(a0, Eb);
        Sfin[s0 + 1] = make_float2(a1, Eb);
        Sfin[s0 + 2] = make_float2(a2, Eb);
        Sfin[s0 + 3] = make_float2(a3, Eb);
    }

    // Parallel sum of logpmax over t = 0..mel-1 (double partials).
    double acc = 0.0;
    for (int i = tid; i < mel; i += 256) acc += (double)g_qbl[i].y;
#pragma unroll
    for (int o = 16; o; o >>= 1) acc += __shfl_xor_sync(0xffffffffu, acc, o);
    if (lane == 0) red_sh[w] = acc;
    __syncthreads();

    if (tid == 0) {
        double sumL = 0.0;
#pragma unroll
        for (int i = 0; i < NWARP; i++) sumL += red_sh[i];
        const double LN2 = 0.6931471805599453;
        float2 vh = Sfin[2 * tl];
        float2 vl = Sfin[2 * tl - 1];
        double lh = (vh.x > 0.f) ? log((double)vh.x) + (double)__float_as_int(vh.y) * LN2 : -1e300;
        double ll = (vl.x > 0.f) ? log((double)vl.x) + (double)__float_as_int(vl.y) * LN2 : -1e300;
        double mx = fmax(lh, ll), mn = fmin(lh, ll);
        double la = mx + log1p(exp(mn - mx)) + sumL;
        float loss = (la > -5e29) ? (float)(-la / (double)tl) : 0.f;
        d_loss[b] = loss;
    }
}

// -------------------------------------------------------------------------
// Kernel 3: mean over B losses (deterministic warp reduction).
// -------------------------------------------------------------------------
__global__ void reduce_loss(float* __restrict__ out) {
    int lane = threadIdx.x;
    float s = d_loss[lane] + d_loss[lane + 32];
#pragma unroll
    for (int o = 16; o; o >>= 1) s += __shfl_xor_sync(0xffffffffu, s, o);
    if (lane == 0) out[0] = s * (1.0f / (float)BB);
}

extern "C" void kernel_launch(void* const* d_in, const int* in_sizes, int n_in,
                              void* d_out, int out_size) {
    const float* x    = (const float*)d_in[0];
    const int*   tlen = (const int*)d_in[1];
    const int*   mlen = (const int*)d_in[2];
    (void)in_sizes; (void)n_in; (void)out_size;

    const int rows = BB * TT;              // 128000
    const int wpb  = 8;                    // 8 warps (rows) per block
    softmax_rows<<<rows / wpb, wpb * 32>>>(x, tlen);
    ctc_forward<<<BB, 256>>>(tlen, mlen);
    reduce_loss<<<1, 32>>>((float*)d_out);
}